// round 12
// baseline (speedup 1.0000x reference)
#include <cuda_runtime.h>
#include <cuda_fp16.h>

#define T_STEPS 1024
#define BATCH   64
#define ICH     512
#define HCH     512
#define G4      2048
#define NBLK    64
#define NTHR    256

// ---------------- scratch (static device globals; no allocation) ------------
__device__ __align__(16) float  g_xi[134217728];       // [T][B][2048] layer0 xi (512MB)
__device__ __align__(16) __half g_x16[33554432];       // x converted to fp16 (64MB)
__device__ __align__(16) __half g_h0[4][BATCH*HCH];    // layer0 h ring (fragment-packed)
__device__ __align__(16) __half g_h1[4][BATCH*HCH];    // layer1 h ring
__device__ __align__(16) uint4  g_wf0[128*1024];       // layer0 Wh fragment-major (G 0..127)
__device__ __align__(16) uint4  g_wf1[256*1024];       // layer1 {Wi,Wh} fragment-major
__device__ __align__(16) uint4  g_wfi0[128*1024];      // layer0 Wi fragment-major (GEMM B)
__device__ __align__(16) float  g_bias_r[2*G4];        // bi+bh, interleaved, both layers
__device__ int g_cnt;

// ---------------- helpers ---------------------------------------------------
__device__ __forceinline__ void mma_f16(float acc[4],
                                        unsigned a0, unsigned a1, unsigned a2, unsigned a3,
                                        unsigned b0, unsigned b1) {
    asm volatile(
        "mma.sync.aligned.m16n8k16.row.col.f32.f16.f16.f32 "
        "{%0,%1,%2,%3},{%4,%5,%6,%7},{%8,%9},{%0,%1,%2,%3};"
        : "+f"(acc[0]), "+f"(acc[1]), "+f"(acc[2]), "+f"(acc[3])
        : "r"(a0), "r"(a1), "r"(a2), "r"(a3), "r"(b0), "r"(b1));
}
__device__ __forceinline__ float sigmf(float x) {
    return __fdividef(1.f, 1.f + __expf(-x));
}
__device__ __forceinline__ float tanhfast(float x) {
    float e = __expf(2.f * x);
    return 1.f - __fdividef(2.f, e + 1.f);
}
__device__ __forceinline__ int ld_relaxed(const int* p) {
    int v;
    asm volatile("ld.relaxed.gpu.global.b32 %0, [%1];" : "=r"(v) : "l"(p) : "memory");
    return v;
}
__device__ __forceinline__ void red_add_relaxed(int* p, int v) {
    asm volatile("red.relaxed.gpu.global.add.s32 [%0], %1;" :: "l"(p), "r"(v) : "memory");
}
__device__ __forceinline__ void fence_gpu() {
    asm volatile("fence.acq_rel.gpu;" ::: "memory");
}
__device__ __forceinline__ uint4 ldcg4(const uint4* p) { return __ldcg(p); }

// fragment-packed h addressing (NBLK-independent; fixed by the reader pattern)
__device__ __forceinline__ int haddr_of(int batch, int col) {
    int u4i = (batch >> 4) * 1024 + (col >> 4) * 32 + ((batch & 7) << 2) + ((col >> 2) & 3);
    return u4i * 8 + ((batch >> 3) & 1) * 4 + (col & 3);
}

// ---------------- init: reset counter (per graph replay) --------------------
__global__ void k_init() { g_cnt = 0; }

// ---------------- x -> fp16 -------------------------------------------------
__global__ void k_x16(const float* __restrict__ x) {
    size_t i = (size_t)blockIdx.x * 256 + threadIdx.x;
    const float4* src = (const float4*)x + i * 2;
    float4 v0 = src[0], v1 = src[1];
    __half2 h0 = __floats2half2_rn(v0.x, v0.y);
    __half2 h1 = __floats2half2_rn(v0.z, v0.w);
    __half2 h2 = __floats2half2_rn(v1.x, v1.y);
    __half2 h3 = __floats2half2_rn(v1.z, v1.w);
    uint4 o;
    o.x = *(unsigned*)&h0; o.y = *(unsigned*)&h1;
    o.z = *(unsigned*)&h2; o.w = *(unsigned*)&h3;
    *((uint4*)g_x16 + i) = o;
}

// ---------------- bias (bi+bh), interleaved, both layers --------------------
__global__ void k_bias(const float* __restrict__ bi, const float* __restrict__ bh) {
    int idx = blockIdx.x * 1024 + threadIdx.x;
    int l = idx >> 11, np = idx & 2047;
    int s = np & 3, j = np >> 2;
    g_bias_r[idx] = bi[l * G4 + s * 512 + j] + bh[l * G4 + s * 512 + j];
}

// ---------------- weight fragment tables ------------------------------------
// Fragment uint (2 halves): group G (16 interleaved gate rows), m 0..31,
// lane (gr=lane>>2, q=lane&3), uw: nt = uw>>1, jp = uw&1.
// Interleaved gate row = 16G + nt*8 + gr (raw row s*512+j, s=row&3, j=row>>2),
// k = 16m + 4q + 2jp + {0,1}.
__global__ void k_wfrag(const float* __restrict__ Wi, const float* __restrict__ Wh) {
    unsigned idx = blockIdx.x * 256u + threadIdx.x;
    if (idx >= 2097152u) return;
    unsigned fi, G, m, lane, uw;
    const float* src;
    unsigned* dst;
    if (idx < 524288u) {
        fi = idx; dst = (unsigned*)g_wf0;
        G = fi >> 12; m = (fi >> 7) & 31; lane = (fi >> 2) & 31; uw = fi & 3;
        src = Wh;
    } else if (idx < 1572864u) {
        fi = idx - 524288u; dst = (unsigned*)g_wf1;
        G = fi >> 13;
        unsigned kc = (fi >> 12) & 1;
        m = (fi >> 7) & 31; lane = (fi >> 2) & 31; uw = fi & 3;
        src = (kc == 0) ? (Wi + (size_t)G4 * ICH) : (Wh + (size_t)G4 * HCH);
    } else {
        fi = idx - 1572864u; dst = (unsigned*)g_wfi0;
        G = fi >> 12; m = (fi >> 7) & 31; lane = (fi >> 2) & 31; uw = fi & 3;
        src = Wi;
    }
    int nt = uw >> 1, jp = uw & 1;
    int gr = lane >> 2, q = lane & 3;
    int rowp = 16 * G + nt * 8 + gr;
    int s = rowp & 3, jr = rowp >> 2;
    int k = 16 * m + 4 * q + 2 * jp;
    const float* p = src + (size_t)(s * 512 + jr) * 512 + k;
    __half2 h = __floats2half2_rn(p[0], p[1]);
    dst[fi] = *(unsigned*)&h;
}

// ---------------- layer0 input-projection GEMM ------------------------------
// C[65536, 2048] = x16[65536, 512] x Wi0[2048, 512]^T + bias0
__global__ __launch_bounds__(256) void k_gemm() {
    __shared__ unsigned As[128][20];

    int n0 = blockIdx.x * 64, m0 = blockIdx.y * 128;
    int tid = threadIdx.x, lane = tid & 31, warp = tid >> 5;
    int q = lane & 3, gr = lane >> 2;
    int wm = warp & 3, wn = warp >> 2;
    int Gb = (n0 >> 4) + wn * 2;

    float acc[2][4][4];
#pragma unroll
    for (int mi = 0; mi < 2; mi++)
#pragma unroll
        for (int ni = 0; ni < 4; ni++)
#pragma unroll
            for (int e = 0; e < 4; e++) acc[mi][ni][e] = 0.f;

    for (int k0 = 0; k0 < 512; k0 += 32) {
#pragma unroll
        for (int i = 0; i < 2; i++) {
            int f = tid + i * 256;
            int r = f >> 2, seg = f & 3;
            uint4 v = *(const uint4*)&g_x16[(size_t)(m0 + r) * 512 + k0 + seg * 8];
            *(uint4*)&As[r][seg * 4] = v;
        }
        __syncthreads();

#pragma unroll
        for (int kt = 0; kt < 2; kt++) {
            int m = (k0 >> 4) + kt;
            uint4 w0 = __ldg(&g_wfi0[(size_t)Gb * 1024 + m * 32 + lane]);
            uint4 w1 = __ldg(&g_wfi0[(size_t)(Gb + 1) * 1024 + m * 32 + lane]);
            unsigned a[2][4];
#pragma unroll
            for (int mi = 0; mi < 2; mi++) {
                int r0 = wm * 32 + mi * 16 + gr;
                uint2 ua = *(uint2*)&As[r0][kt * 8 + 2 * q];
                uint2 ub = *(uint2*)&As[r0 + 8][kt * 8 + 2 * q];
                a[mi][0] = ua.x; a[mi][1] = ub.x; a[mi][2] = ua.y; a[mi][3] = ub.y;
            }
#pragma unroll
            for (int mi = 0; mi < 2; mi++) {
                mma_f16(acc[mi][0], a[mi][0], a[mi][1], a[mi][2], a[mi][3], w0.x, w0.y);
                mma_f16(acc[mi][1], a[mi][0], a[mi][1], a[mi][2], a[mi][3], w0.z, w0.w);
                mma_f16(acc[mi][2], a[mi][0], a[mi][1], a[mi][2], a[mi][3], w1.x, w1.y);
                mma_f16(acc[mi][3], a[mi][0], a[mi][1], a[mi][2], a[mi][3], w1.z, w1.w);
            }
        }
        __syncthreads();
    }

#pragma unroll
    for (int mi = 0; mi < 2; mi++)
#pragma unroll
        for (int ni = 0; ni < 4; ni++) {
            int row  = m0 + wm * 32 + mi * 16 + gr;
            int ncol = n0 + wn * 32 + (ni >> 1) * 16 + (ni & 1) * 8 + 2 * q;
            float2 bb = *(const float2*)&g_bias_r[ncol];
            float2 o;
            o.x = acc[mi][ni][0] + bb.x; o.y = acc[mi][ni][1] + bb.y;
            *(float2*)&g_xi[(size_t)row * G4 + ncol] = o;
            o.x = acc[mi][ni][2] + bb.x; o.y = acc[mi][ni][3] + bb.y;
            *(float2*)&g_xi[(size_t)(row + 8) * G4 + ncol] = o;
        }
}

// ---------------- fused 2-layer persistent recurrent kernel -----------------
// 64 blocks x 256 threads (8 warps: chunk = w&3 batch-group, half = w>>2
// K-half). Block b owns gate' rows [32b,32b+32) = groups {2b,2b+1} <-> h cols
// [8b,8b+8) for BOTH layers.  Round r: L0 step r (warp: 16 m, 64 mma) and
// L1 step r-2 (warp: 32 m of Wi1|Wh1 by half, 128 mma).  Halving the block
// count halves the per-round h broadcast traffic (192KB/block * 64 = 12MB).
__global__ __launch_bounds__(NTHR, 1) void k_fused(const float* __restrict__ h0in,
                                                   const float* __restrict__ c0in,
                                                   float* __restrict__ y,
                                                   float* __restrict__ hT,
                                                   float* __restrict__ cT) {
    __shared__ float sGp[4][64][36];   // [0,1]=L0 K-halves, [2,3]=L1 K-halves

    int b = blockIdx.x, tid = threadIdx.x;
    int lane = tid & 31, w = tid >> 5;
    int q = lane & 3, gr = lane >> 2;
    int chunk = w & 3, half = w >> 2;

    int batch = tid >> 2, jl = tid & 3;
    int colA = 8 * b + jl, colB = colA + 4;
    int hadA = haddr_of(batch, colA), hadB = haddr_of(batch, colB);

    // init c and h_0 for both layers, publish (arrival #1)
    float c0A = c0in[batch * HCH + colA];
    float c0B = c0in[batch * HCH + colB];
    float c1A = c0in[BATCH * HCH + batch * HCH + colA];
    float c1B = c0in[BATCH * HCH + batch * HCH + colB];
    ((__half*)g_h0[0])[hadA] = __float2half_rn(h0in[batch * HCH + colA]);
    ((__half*)g_h0[0])[hadB] = __float2half_rn(h0in[batch * HCH + colB]);
    ((__half*)g_h1[0])[hadA] = __float2half_rn(h0in[BATCH * HCH + batch * HCH + colA]);
    ((__half*)g_h1[0])[hadB] = __float2half_rn(h0in[BATCH * HCH + batch * HCH + colB]);
    __syncthreads();
    if (tid == 0) { fence_gpu(); red_add_relaxed(&g_cnt, 1); }

    float4 bbA = *(const float4*)&g_bias_r[G4 + 32 * b + 4 * jl];
    float4 bbB = *(const float4*)&g_bias_r[G4 + 32 * b + 16 + 4 * jl];

    const int loff = chunk * 1024 + lane;
    const uint4* wA0 = g_wf0 + (size_t)(2 * b) * 1024 + lane;
    const uint4* wA1 = g_wf0 + (size_t)(2 * b + 1) * 1024 + lane;
    const uint4* wB0 = g_wf1 + (size_t)((2 * b) * 2 + half) * 1024 + lane;
    const uint4* wB1 = g_wf1 + (size_t)((2 * b + 1) * 2 + half) * 1024 + lane;
    const int mA0 = 16 * half;

    for (int r = 0; r < 1026; ++r) {
        // prefetch xi_r before the wait
        float4 xvA = make_float4(0.f, 0.f, 0.f, 0.f);
        float4 xvB = xvA;
        if (r < T_STEPS) {
            const float* xit = g_xi + (size_t)r * BATCH * G4 + batch * G4 + 32 * b;
            xvA = *(const float4*)&xit[4 * jl];
            xvB = *(const float4*)&xit[16 + 4 * jl];
        }

        // wait: all round r-1 publications visible
        if (tid == 0) {
            int need = (r + 1) * NBLK;
            while (ld_relaxed(&g_cnt) < need) {}
            fence_gpu();
        }
        __syncthreads();

        // ---- phase A: layer0 step r (16 m, 64 mma, groups of 4) ----
        if (r < T_STEPS) {
            const uint4* hA = (const uint4*)g_h0[r & 3] + loff;
            float acc[2][2][4] = {{{0.f,0.f,0.f,0.f},{0.f,0.f,0.f,0.f}},
                                  {{0.f,0.f,0.f,0.f},{0.f,0.f,0.f,0.f}}};
            uint4 hr[2][4], w0[2][4], w1[2][4];
#pragma unroll
            for (int u = 0; u < 4; u++) {
                int m = mA0 + u;
                hr[0][u] = ldcg4(hA + m * 32);
                w0[0][u] = __ldg(wA0 + m * 32);
                w1[0][u] = __ldg(wA1 + m * 32);
            }
#pragma unroll
            for (int gs = 0; gs < 4; gs++) {
                int cur = gs & 1;
                if (gs < 3) {
#pragma unroll
                    for (int u = 0; u < 4; u++) {
                        int m = mA0 + 4 * (gs + 1) + u;
                        hr[cur ^ 1][u] = ldcg4(hA + m * 32);
                        w0[cur ^ 1][u] = __ldg(wA0 + m * 32);
                        w1[cur ^ 1][u] = __ldg(wA1 + m * 32);
                    }
                }
#pragma unroll
                for (int u = 0; u < 4; u++) {
                    uint4 h4 = hr[cur][u];
                    mma_f16(acc[0][0], h4.x, h4.z, h4.y, h4.w, w0[cur][u].x, w0[cur][u].y);
                    mma_f16(acc[0][1], h4.x, h4.z, h4.y, h4.w, w0[cur][u].z, w0[cur][u].w);
                    mma_f16(acc[1][0], h4.x, h4.z, h4.y, h4.w, w1[cur][u].x, w1[cur][u].y);
                    mma_f16(acc[1][1], h4.x, h4.z, h4.y, h4.w, w1[cur][u].z, w1[cur][u].w);
                }
            }
#pragma unroll
            for (int g2 = 0; g2 < 2; g2++)
#pragma unroll
                for (int nt = 0; nt < 2; nt++) {
                    int lcol = g2 * 16 + nt * 8 + 2 * q;
                    *(float2*)&sGp[half][16 * chunk + gr][lcol] =
                        make_float2(acc[g2][nt][0], acc[g2][nt][1]);
                    *(float2*)&sGp[half][16 * chunk + gr + 8][lcol] =
                        make_float2(acc[g2][nt][2], acc[g2][nt][3]);
                }
        }

        // ---- phase B: layer1 step r-2 (32 m, 128 mma, groups of 4) ----
        if (r >= 2) {
            const uint4* hB = (half == 0)
                ? (const uint4*)g_h0[(r - 1) & 3] + loff     // x-input = L0 step r-2 out
                : (const uint4*)g_h1[(r - 2) & 3] + loff;    // recurrent = L1 step r-3 out
            float acc[2][2][4] = {{{0.f,0.f,0.f,0.f},{0.f,0.f,0.f,0.f}},
                                  {{0.f,0.f,0.f,0.f},{0.f,0.f,0.f,0.f}}};
            uint4 hr[2][4], w0[2][4], w1[2][4];
#pragma unroll
            for (int u = 0; u < 4; u++) {
                hr[0][u] = ldcg4(hB + u * 32);
                w0[0][u] = __ldg(wB0 + u * 32);
                w1[0][u] = __ldg(wB1 + u * 32);
            }
#pragma unroll
            for (int gs = 0; gs < 8; gs++) {
                int cur = gs & 1;
                if (gs < 7) {
#pragma unroll
                    for (int u = 0; u < 4; u++) {
                        int m = 4 * (gs + 1) + u;
                        hr[cur ^ 1][u] = ldcg4(hB + m * 32);
                        w0[cur ^ 1][u] = __ldg(wB0 + m * 32);
                        w1[cur ^ 1][u] = __ldg(wB1 + m * 32);
                    }
                }
#pragma unroll
                for (int u = 0; u < 4; u++) {
                    uint4 h4 = hr[cur][u];
                    mma_f16(acc[0][0], h4.x, h4.z, h4.y, h4.w, w0[cur][u].x, w0[cur][u].y);
                    mma_f16(acc[0][1], h4.x, h4.z, h4.y, h4.w, w0[cur][u].z, w0[cur][u].w);
                    mma_f16(acc[1][0], h4.x, h4.z, h4.y, h4.w, w1[cur][u].x, w1[cur][u].y);
                    mma_f16(acc[1][1], h4.x, h4.z, h4.y, h4.w, w1[cur][u].z, w1[cur][u].w);
                }
            }
#pragma unroll
            for (int g2 = 0; g2 < 2; g2++)
#pragma unroll
                for (int nt = 0; nt < 2; nt++) {
                    int lcol = g2 * 16 + nt * 8 + 2 * q;
                    *(float2*)&sGp[2 + half][16 * chunk + gr][lcol] =
                        make_float2(acc[g2][nt][0], acc[g2][nt][1]);
                    *(float2*)&sGp[2 + half][16 * chunk + gr + 8][lcol] =
                        make_float2(acc[g2][nt][2], acc[g2][nt][3]);
                }
        }
        __syncthreads();

        // ---- cells: sum K-half partials, update, publish ----
        float hv1A = 0.f, hv1B = 0.f;
        if (r < T_STEPS) {
            float4 pa, pb;
            // col A (local gate 4*jl)
            pa = *(const float4*)&sGp[0][batch][4 * jl];
            pb = *(const float4*)&sGp[1][batch][4 * jl];
            {
                float f  = sigmf(pa.x + pb.x + xvA.x);
                float ii = sigmf(pa.y + pb.y + xvA.y);
                float o  = sigmf(pa.z + pb.z + xvA.z);
                float g  = tanhfast(pa.w + pb.w + xvA.w);
                float c  = c0A * f + ii * g;
                c0A = c;
                float h  = o * tanhfast(c);
                ((__half*)g_h0[(r + 1) & 3])[hadA] = __float2half_rn(h);
                if (r == T_STEPS - 1) { hT[batch * HCH + colA] = h; cT[batch * HCH + colA] = c; }
            }
            // col B (local gate 16 + 4*jl)
            pa = *(const float4*)&sGp[0][batch][16 + 4 * jl];
            pb = *(const float4*)&sGp[1][batch][16 + 4 * jl];
            {
                float f  = sigmf(pa.x + pb.x + xvB.x);
                float ii = sigmf(pa.y + pb.y + xvB.y);
                float o  = sigmf(pa.z + pb.z + xvB.z);
                float g  = tanhfast(pa.w + pb.w + xvB.w);
                float c  = c0B * f + ii * g;
                c0B = c;
                float h  = o * tanhfast(c);
                ((__half*)g_h0[(r + 1) & 3])[hadB] = __float2half_rn(h);
                if (r == T_STEPS - 1) { hT[batch * HCH + colB] = h; cT[batch * HCH + colB] = c; }
            }
        }
        if (r >= 2) {
            float4 pa, pb;
            pa = *(const float4*)&sGp[2][batch][4 * jl];
            pb = *(const float4*)&sGp[3][batch][4 * jl];
            {
                float f  = sigmf(pa.x + pb.x + bbA.x);
                float ii = sigmf(pa.y + pb.y + bbA.y);
                float o  = sigmf(pa.z + pb.z + bbA.z);
                float g  = tanhfast(pa.w + pb.w + bbA.w);
                float c  = c1A * f + ii * g;
                c1A = c;
                hv1A = o * tanhfast(c);
                ((__half*)g_h1[(r - 1) & 3])[hadA] = __float2half_rn(hv1A);
            }
            pa = *(const float4*)&sGp[2][batch][16 + 4 * jl];
            pb = *(const float4*)&sGp[3][batch][16 + 4 * jl];
            {
                float f  = sigmf(pa.x + pb.x + bbB.x);
                float ii = sigmf(pa.y + pb.y + bbB.y);
                float o  = sigmf(pa.z + pb.z + bbB.z);
                float g  = tanhfast(pa.w + pb.w + bbB.w);
                float c  = c1B * f + ii * g;
                c1B = c;
                hv1B = o * tanhfast(c);
                ((__half*)g_h1[(r - 1) & 3])[hadB] = __float2half_rn(hv1B);
            }
        }
        __syncthreads();
        if (tid == 0 && r < 1025) { fence_gpu(); red_add_relaxed(&g_cnt, 1); }

        // ---- off-critical-path outputs ----
        if (r >= 2) {
            float* yt = y + (size_t)(r - 2) * BATCH * HCH + batch * HCH;
            yt[colA] = hv1A;
            yt[colB] = hv1B;
            if (r == 1025) {
                hT[BATCH * HCH + batch * HCH + colA] = hv1A;
                cT[BATCH * HCH + batch * HCH + colA] = c1A;
                hT[BATCH * HCH + batch * HCH + colB] = hv1B;
                cT[BATCH * HCH + batch * HCH + colB] = c1B;
            }
        }
    }
}

// ---------------- launch ----------------------------------------------------
extern "C" void kernel_launch(void* const* d_in, const int* in_sizes, int n_in,
                              void* d_out, int out_size) {
    const float* x  = (const float*)d_in[0];
    const float* Wi = (const float*)d_in[1];
    const float* bi = (const float*)d_in[2];
    const float* Wh = (const float*)d_in[3];
    const float* bh = (const float*)d_in[4];
    const float* h0 = (const float*)d_in[5];
    const float* c0 = (const float*)d_in[6];

    float* out = (float*)d_out;
    float* y   = out;                                   // [T,B,HC]
    float* hsO = out + (size_t)T_STEPS * BATCH * HCH;   // [L,B,HC]
    float* csO = hsO + (size_t)2 * BATCH * HCH;         // [L,B,HC]

    k_x16<<<16384, 256>>>(x);
    k_bias<<<4, 1024>>>(bi, bh);
    k_wfrag<<<8192, 256>>>(Wi, Wh);
    k_gemm<<<dim3(32, 512), 256>>>();
    k_init<<<1, 1>>>();
    k_fused<<<NBLK, NTHR>>>(h0, c0, y, hsO, csO);

    (void)in_sizes; (void)n_in; (void)out_size;
}